// round 9
// baseline (speedup 1.0000x reference)
#include <cuda_runtime.h>
#include <cstdint>

#define LOCN  10000
#define DLOC  128
#define DST   64
#define DSUM  256
#define BB    64
#define SS    128
#define NIDX  (BB * SS)        // 8192 loc entries (with duplicates)
#define NQ    4                // quarters per row
#define QLEN  625              // float4 per quarter (2500/4)
#define NITEMS (NIDX * NQ)     // 32768 work items
#define NBLK  296              // 2 blocks/SM x 148 SMs

// Partial sums: g_Yp[q][row][d], 4 x 5.12 MB. Raw (no bias/relu) — combined
// in the gather kernel. Only claimed rows are ever read.
__device__ float g_Yp[NQ][(size_t)LOCN * DLOC];
__device__ int   g_flag4[NQ * LOCN];  // epoch-tagged claims (never cleared)
__device__ int   g_work;              // work-stealing cursor over items
__device__ int   g_epoch;             // bumped by gather kernel each launch

// ---------------------------------------------------------------------------
// Kernel 1: prologue writes the Y-independent output regions (st/ed/yt),
// then persistent warps steal (token, quarter) items: first to claim
// (row, q) streams A[row][q*2500/4 .. ) and stores raw partial sums.
// ---------------------------------------------------------------------------
__global__ void __launch_bounds__(256, 2) spmm_kernel(
    const int*   __restrict__ loc,
    const int*   __restrict__ st,
    const int*   __restrict__ ed,
    const float* __restrict__ A,
    const float* __restrict__ W,
    const float* __restrict__ emb_st,
    const float* __restrict__ emb_ed,
    float4*      __restrict__ out)
{
    const int tid  = blockIdx.x * 256 + threadIdx.x;
    const int lane = threadIdx.x & 31;
    const int e    = g_epoch + 1;

    // ---------- Phase A: non-Y outputs (st / ed / yt), grid-stride --------
    {
        constexpr int N1V = NIDX * (DSUM / 4);      // 524288 (res region)
        constexpr int NJ  = NIDX * 48;              // 393216 non-Y float4
        const float4* __restrict__ stv = reinterpret_cast<const float4*>(emb_st);
        const float4* __restrict__ edv = reinterpret_cast<const float4*>(emb_ed);
        const float s = 16.0f;

        for (int j = tid; j < NJ; j += NBLK * 256) {
            const int token = j / 48;
            const int k     = j - token * 48;
            if (k < 16) {                       // st branch, d4 = 32+k
                float4 r = stv[st[token] * 16 + k];
                r.x *= s; r.y *= s; r.z *= s; r.w *= s;
                out[token * 64 + 32 + k] = r;
            } else if (k < 32) {                // ed branch, d4 = 48+(k-16)
                float4 r = edv[ed[token] * 16 + (k - 16)];
                r.x *= s; r.y *= s; r.z *= s; r.w *= s;
                out[token * 64 + 32 + k] = r;
            } else {                            // yt region (NOT scaled)
                const int kk = k - 32;
                const int ss = token & (SS - 1);
                const int yt = (ss < SS - 1) ? st[token + 1] : 0;
                out[N1V + token * 16 + kk] = stv[yt * 16 + kk];
            }
        }
    }

    // ---------- Phase B: work-stealing quarter-row SpMM --------------------
    constexpr int K   = 8;                     // float4 per lane per iter
    constexpr int VPI = 32 * K;                // 256 float4/warp/iter
    constexpr int NIT = (QLEN + VPI - 1) / VPI;// 3
    const float4 Z = make_float4(0.f, 0.f, 0.f, 0.f);

    for (;;) {
        int widx = 0, claimed = 0, row_idx = 0;
        if (lane == 0) {
            widx = atomicAdd(&g_work, 1);
            if (widx < NITEMS) {
                const int q = widx >> 13;              // item / 8192
                const int i = widx & (NIDX - 1);
                const int r = __ldg(&loc[i]);
                claimed = (atomicExch(&g_flag4[q * LOCN + r], e) != e);
                row_idx = (q << 16) | r;               // pack q + row
            }
        }
        widx    = __shfl_sync(0xffffffffu, widx, 0);
        if (widx >= NITEMS) return;
        claimed = __shfl_sync(0xffffffffu, claimed, 0);
        if (!claimed) continue;
        row_idx = __shfl_sync(0xffffffffu, row_idx, 0);
        const int q   = row_idx >> 16;
        const int row = row_idx & 0xffff;

        const float4* __restrict__ rp =
            reinterpret_cast<const float4*>(A + (size_t)row * LOCN);
        const int qstart = q * QLEN;
        const int qend   = qstart + QLEN;

        float acc0 = 0.f, acc1 = 0.f, acc2 = 0.f, acc3 = 0.f;

        float4 cur[K], nxt[K];
        #pragma unroll
        for (int k = 0; k < K; ++k) {
            const int idx = qstart + lane + 32 * k;
            cur[k] = (idx < qend) ? __ldcs(&rp[idx]) : Z;
        }

        for (int it = 0; it < NIT; ++it) {
            if (it + 1 < NIT) {
                const int nbase = qstart + (it + 1) * VPI + lane;
                #pragma unroll
                for (int k = 0; k < K; ++k) {
                    const int idx = nbase + 32 * k;
                    nxt[k] = (idx < qend) ? __ldcs(&rp[idx]) : Z;
                }
            }

            #pragma unroll
            for (int k = 0; k < K; ++k) {
                const float4 v = cur[k];
                const bool nz = (v.x != 0.f) | (v.y != 0.f) |
                                (v.z != 0.f) | (v.w != 0.f);
                unsigned m = __ballot_sync(0xffffffffu, nz);
                while (m) {
                    const int j = __ffs(m) - 1;
                    m &= m - 1;
                    const float vx = __shfl_sync(0xffffffffu, v.x, j);
                    const float vy = __shfl_sync(0xffffffffu, v.y, j);
                    const float vz = __shfl_sync(0xffffffffu, v.z, j);
                    const float vw = __shfl_sync(0xffffffffu, v.w, j);
                    const int n0 = (qstart + it * VPI + k * 32 + j) * 4;

                    const float* __restrict__ Wr = W + (size_t)n0 * DLOC + lane;
                    if (vx != 0.f) {
                        acc0 = fmaf(vx, Wr[0],  acc0);
                        acc1 = fmaf(vx, Wr[32], acc1);
                        acc2 = fmaf(vx, Wr[64], acc2);
                        acc3 = fmaf(vx, Wr[96], acc3);
                    }
                    Wr += DLOC;
                    if (vy != 0.f) {
                        acc0 = fmaf(vy, Wr[0],  acc0);
                        acc1 = fmaf(vy, Wr[32], acc1);
                        acc2 = fmaf(vy, Wr[64], acc2);
                        acc3 = fmaf(vy, Wr[96], acc3);
                    }
                    Wr += DLOC;
                    if (vz != 0.f) {
                        acc0 = fmaf(vz, Wr[0],  acc0);
                        acc1 = fmaf(vz, Wr[32], acc1);
                        acc2 = fmaf(vz, Wr[64], acc2);
                        acc3 = fmaf(vz, Wr[96], acc3);
                    }
                    Wr += DLOC;
                    if (vw != 0.f) {
                        acc0 = fmaf(vw, Wr[0],  acc0);
                        acc1 = fmaf(vw, Wr[32], acc1);
                        acc2 = fmaf(vw, Wr[64], acc2);
                        acc3 = fmaf(vw, Wr[96], acc3);
                    }
                }
            }

            #pragma unroll
            for (int k = 0; k < K; ++k) cur[k] = nxt[k];
        }

        float* __restrict__ y = g_Yp[q] + (size_t)row * DLOC + lane;
        y[0]  = acc0;
        y[32] = acc1;
        y[64] = acc2;
        y[96] = acc3;
    }
}

// ---------------------------------------------------------------------------
// Kernel 2: loc-branch of the output. One float4 per thread:
//   out[token*64 + d4] = relu(sum_q Yp[q][loc] + bias) * 16, d4 in [0,32).
// Also resets bookkeeping for the next launch.
// ---------------------------------------------------------------------------
__global__ void __launch_bounds__(256) gather_loc_kernel(
    const int*   __restrict__ loc,
    const float* __restrict__ bias,
    float4*      __restrict__ out)
{
    constexpr int NLV = NIDX * 32;               // 262144 float4
    const int idx = blockIdx.x * 256 + threadIdx.x;
    if (idx >= NLV) return;

    if (idx == 0) {
        g_epoch = g_epoch + 1;
        g_work  = 0;
    }

    const int bs = idx >> 5;
    const int d4 = idx & 31;
    const size_t off = (size_t)loc[bs] * 32 + d4;

    const float4* __restrict__ y0 = reinterpret_cast<const float4*>(g_Yp[0]);
    const float4* __restrict__ y1 = reinterpret_cast<const float4*>(g_Yp[1]);
    const float4* __restrict__ y2 = reinterpret_cast<const float4*>(g_Yp[2]);
    const float4* __restrict__ y3 = reinterpret_cast<const float4*>(g_Yp[3]);
    const float4 a = y0[off], b = y1[off], c = y2[off], d = y3[off];
    const float4 bv = reinterpret_cast<const float4*>(bias)[d4];

    float4 r;
    r.x = fmaxf(a.x + b.x + c.x + d.x + bv.x, 0.f) * 16.0f;
    r.y = fmaxf(a.y + b.y + c.y + d.y + bv.y, 0.f) * 16.0f;
    r.z = fmaxf(a.z + b.z + c.z + d.z + bv.z, 0.f) * 16.0f;
    r.w = fmaxf(a.w + b.w + c.w + d.w + bv.w, 0.f) * 16.0f;

    out[bs * 64 + d4] = r;
}

extern "C" void kernel_launch(void* const* d_in, const int* in_sizes, int n_in,
                              void* d_out, int out_size)
{
    const int*   loc    = (const int*)  d_in[0];
    const int*   st     = (const int*)  d_in[1];
    const int*   ed     = (const int*)  d_in[2];
    const float* A      = (const float*)d_in[3];
    const float* W_loc  = (const float*)d_in[4];
    const float* b_loc  = (const float*)d_in[5];
    const float* emb_st = (const float*)d_in[6];
    const float* emb_ed = (const float*)d_in[7];

    spmm_kernel<<<NBLK, 256>>>(loc, st, ed, A, W_loc, emb_st, emb_ed,
                               (float4*)d_out);

    constexpr int nlv = NIDX * 32;
    gather_loc_kernel<<<nlv / 256, 256>>>(loc, b_loc, (float4*)d_out);
}